// round 9
// baseline (speedup 1.0000x reference)
#include <cuda_runtime.h>

#define NN   100000
#define NE   1600000
#define INF  128
#define HF   64
#define OUTF 32

#define PREP_B   256
#define PREP_G   592                      // 4 per SM on 148 SMs: all co-resident
#define NPB      ((NN + PREP_G - 1) / PREP_G)   // 169 nodes per block

// ---- scratch (static device globals; no allocation anywhere) ----
__device__ __align__(16) float g_deg   [NN];
__device__ __align__(16) float g_dinv  [NN];
__device__ __align__(16) int   g_cnt   [NN];      // in-degree histogram (by col)
__device__ __align__(16) int   g_cursor[NN];      // CSR fill cursors
__device__ __align__(16) int   g_off   [NN + 1];  // CSR offsets (exclusive)
__device__ __align__(16) int   g_bsum  [PREP_G];  // per-block count totals
__device__ __align__(16) int2  g_csr   [NE];      // packed (src_row, norm-bits)
__device__ __align__(16) float g_h1 [NN * HF];    // X @ W1
__device__ __align__(16) float g_z1 [NN * HF];    // relu(agg1 + b1)
__device__ __align__(16) float g_h2 [NN * OUTF];  // z1 @ W2
__device__ unsigned int g_flag;                   // 0 = int64 edge_index, 1 = int32

// ---- packed f32x2 helpers (Blackwell FFMA2) ----
__device__ __forceinline__ unsigned long long pack2(float x) {
    unsigned long long r;
    asm("mov.b64 %0, {%1, %2};" : "=l"(r) : "f"(x), "f"(x));
    return r;
}
__device__ __forceinline__ unsigned long long fma2(unsigned long long a,
                                                   unsigned long long b,
                                                   unsigned long long c) {
    unsigned long long d;
    asm("fma.rn.f32x2 %0, %1, %2, %3;" : "=l"(d) : "l"(a), "l"(b), "l"(c));
    return d;
}
__device__ __forceinline__ float2 unpack2(unsigned long long v) {
    float lo, hi;
    asm("mov.b64 {%0, %1}, %2;" : "=f"(lo), "=f"(hi) : "l"(v));
    return make_float2(lo, hi);
}

// ---- software grid barrier (all PREP_G blocks resident by construction) ----
__device__ unsigned g_bar_count = 0;
__device__ volatile unsigned g_bar_gen = 0;

__device__ __forceinline__ void grid_barrier() {
    __syncthreads();
    if (threadIdx.x == 0) {
        unsigned gen = g_bar_gen;
        __threadfence();
        if (atomicAdd(&g_bar_count, 1u) == PREP_G - 1) {
            g_bar_count = 0;
            __threadfence();
            g_bar_gen = gen + 1;
        } else {
            while (g_bar_gen == gen) { }
            __threadfence();
        }
    }
    __syncthreads();
}

// ---------------------------------------------------------------
// initA: per-call scratch init.
__global__ void k_initA() {
    int i = blockIdx.x * 256 + threadIdx.x;
    if (i < NN) {
        g_deg[i] = 1.0f;    // self-loop weight
        g_cnt[i] = 0;
        g_cursor[i] = 0;
    }
    if (i == 0) g_flag = 0u;
}

// initB: sampled dtype detect. int64 (values in [0,2^31)): odd u32 words all 0.
__global__ void k_initB(const unsigned int* __restrict__ ei32) {
    int s = (int)threadIdx.x * (NE / 256) + 1;   // 256 spread samples
    if (ei32[2 * s + 1] != 0u) atomicOr(&g_flag, 1u);
}

// ---------------------------------------------------------------
// k_prep: decode+atomics -> bar -> dinv+scan -> bar -> prefix -> bar -> fill.
__global__ __launch_bounds__(PREP_B) void k_prep(const int* __restrict__ ei32,
                                                 const float* __restrict__ ew) {
    int t = threadIdx.x, b = blockIdx.x;
    int lane = t & 31, wid = t >> 5;
    int stride = PREP_G * PREP_B;
    int flag = g_flag;

    // --- phase 1: degree/count atomics ---
    for (int e = b * PREP_B + t; e < NE; e += stride) {
        int c;
        if (flag) c = ei32[NE + e];          // int32: [row[NE], col[NE]]
        else      c = ei32[2 * (NE + e)];    // int64: low word
        atomicAdd(&g_deg[c], ew[e]);
        atomicAdd(&g_cnt[c], 1);
    }

    grid_barrier();

    // --- phase 2: dinv + per-block scan ---
    int i = b * NPB + t;                       // NPB=169 < 256
    bool valid = (t < NPB) && (i < NN);

    if (valid) g_dinv[i] = rsqrtf(g_deg[i]);   // deg >= 1 always

    int v = valid ? g_cnt[i] : 0;

    int val = v;
#pragma unroll
    for (int s = 1; s < 32; s <<= 1) {
        int u = __shfl_up_sync(0xffffffffu, val, s);
        if (lane >= s) val += u;
    }
    __shared__ int wsum[8];
    if (lane == 31) wsum[wid] = val;
    __syncthreads();
    __shared__ int wexc[8];
    if (t == 0) {
        int s = 0;
#pragma unroll
        for (int w = 0; w < 8; w++) { wexc[w] = s; s += wsum[w]; }
        g_bsum[b] = s;                          // block total
    }
    __syncthreads();
    int excl = wexc[wid] + val - v;
    if (valid) g_off[i] = excl;                 // local exclusive (prefix later)

    grid_barrier();

    // --- phase 3: cross-block prefix (each block redundantly) ---
    __shared__ int red[PREP_B];
    int p = 0;
    for (int j = t; j < b; j += PREP_B) p += g_bsum[j];
    red[t] = p;
    __syncthreads();
#pragma unroll
    for (int s = 128; s > 0; s >>= 1) {
        if (t < s) red[t] += red[t + s];
        __syncthreads();
    }
    int prefix = red[0];
    if (valid) g_off[i] += prefix;
    if (b == 0 && t == 0) g_off[NN] = NE;

    grid_barrier();

    // --- phase 4: CSR fill with fused norm; packed (row, norm) int2 ---
    for (int e = b * PREP_B + t; e < NE; e += stride) {
        int r, c;
        if (flag) { r = ei32[e];     c = ei32[NE + e]; }
        else      { r = ei32[2 * e]; c = ei32[2 * (NE + e)]; }
        int pos = g_off[c] + atomicAdd(&g_cursor[c], 1);
        float nm = g_dinv[r] * ew[e] * g_dinv[c];
        g_csr[pos] = make_int2(r, __float_as_int(nm));
    }
}

// ---------------------------------------------------------------
// GEMM1: H1 = X[NN,128] @ W1[128,64], FFMA2, occupancy-tuned.
// 128 nodes/block, 256 threads; thread = 4 nodes (j*32+ng) x 8 outputs (4 pairs).
// 2 k-stages of 64. Xs[128][68] (34.8KB) + Wsh[8][1028] (32.9KB) = 67.7KB
// -> 3 blocks/SM (smem 203KB, regs capped by __launch_bounds__(256,3)).
#define G1_XS    (128 * 68)
#define G1_WS    (8 * 1028)
#define G1_SMEM  ((G1_XS + G1_WS) * 4)         // 67712 B

__global__ __launch_bounds__(256, 3) void k_gemm1(const float* __restrict__ x,
                                                  const float* __restrict__ W1) {
    extern __shared__ float sh[];
    float* Xs  = sh;           // [128][68]
    float* Wsh = sh + G1_XS;   // [8][1028]  (fg-major, 8 floats per k, pad 4)

    int nb = blockIdx.x * 128;
    int tid = threadIdx.x;
    int fg = tid & 7;          // output pairs: f = fg*8 .. fg*8+7
    int ng = tid >> 3;         // 0..31; nodes: j*32 + ng

    // Load W1 (128x64) into conflict-free layout: bank(4fg + 8k) -> 1 phase.
    for (int i = tid; i < 128 * 16; i += 256) {
        int k = i >> 4, c = i & 15;            // c = float4 index in row
        int fgw = c >> 1, half = (c & 1) * 4;
        float4 v = ((const float4*)W1)[i];
        *(float4*)&Wsh[fgw * 1028 + k * 8 + half] = v;
    }

    unsigned long long acc[4][4];   // [node][output-pair]
#pragma unroll
    for (int j = 0; j < 4; j++)
#pragma unroll
        for (int p = 0; p < 4; p++) acc[j][p] = 0ull;

#pragma unroll
    for (int stage = 0; stage < 2; stage++) {
        // stage k-range: [stage*64, stage*64+64)
        for (int i = tid; i < 128 * 16; i += 256) {
            int node = i >> 4, kc = i & 15;
            int gn = nb + node;
            float4 v = make_float4(0.f, 0.f, 0.f, 0.f);
            if (gn < NN) v = ((const float4*)x)[gn * 32 + stage * 16 + kc];
            *(float4*)&Xs[node * 68 + kc * 4] = v;
        }
        __syncthreads();

#pragma unroll 2
        for (int kc = 0; kc < 16; kc++) {      // 4 k per iter
            float4 xv[4];
#pragma unroll
            for (int j = 0; j < 4; j++)
                xv[j] = ((const float4*)Xs)[(j * 32 + ng) * 17 + kc];
#pragma unroll
            for (int q = 0; q < 4; q++) {
                int kf = stage * 64 + kc * 4 + q;
                const float* wp = &Wsh[fg * 1028 + kf * 8];
                ulonglong2 wa = *(const ulonglong2*)wp;
                ulonglong2 wb = *(const ulonglong2*)(wp + 4);
#pragma unroll
                for (int j = 0; j < 4; j++) {
                    float xs = (q == 0) ? xv[j].x : (q == 1) ? xv[j].y
                             : (q == 2) ? xv[j].z : xv[j].w;
                    unsigned long long xd = pack2(xs);
                    acc[j][0] = fma2(xd, wa.x, acc[j][0]);
                    acc[j][1] = fma2(xd, wa.y, acc[j][1]);
                    acc[j][2] = fma2(xd, wb.x, acc[j][2]);
                    acc[j][3] = fma2(xd, wb.y, acc[j][3]);
                }
            }
        }
        __syncthreads();
    }

#pragma unroll
    for (int j = 0; j < 4; j++) {
        int gn = nb + j * 32 + ng;
        if (gn >= NN) continue;
        float2 p0 = unpack2(acc[j][0]), p1 = unpack2(acc[j][1]);
        float2 p2 = unpack2(acc[j][2]), p3 = unpack2(acc[j][3]);
        ((float4*)g_h1)[gn * 16 + fg * 2]     = make_float4(p0.x, p0.y, p1.x, p1.y);
        ((float4*)g_h1)[gn * 16 + fg * 2 + 1] = make_float4(p2.x, p2.y, p3.x, p3.y);
    }
}

// ---------------------------------------------------------------
// Gather layer 1: 16-lane group per node, float4 per lane (row = 16 x float4).
__global__ __launch_bounds__(256) void k_gather1(const float* __restrict__ b1) {
    int tid = blockIdx.x * 256 + threadIdx.x;
    int c = tid >> 4;
    int sub = threadIdx.x & 15;
    if (c >= NN) return;

    const float4* H = (const float4*)g_h1;     // row stride 16
    float di = g_dinv[c];
    float d2 = di * di;
    float4 hc = H[c * 16 + sub];
    float ax = d2 * hc.x, ay = d2 * hc.y, az = d2 * hc.z, aw = d2 * hc.w;

    int i = g_off[c], end = g_off[c + 1];
    for (; i + 3 < end; i += 4) {
        int2 e0 = g_csr[i],     e1 = g_csr[i + 1];
        int2 e2 = g_csr[i + 2], e3 = g_csr[i + 3];
        float4 h0 = H[e0.x * 16 + sub];
        float4 h1 = H[e1.x * 16 + sub];
        float4 h2 = H[e2.x * 16 + sub];
        float4 h3 = H[e3.x * 16 + sub];
        float n0 = __int_as_float(e0.y), n1 = __int_as_float(e1.y);
        float n2 = __int_as_float(e2.y), n3 = __int_as_float(e3.y);
        ax += n0 * h0.x + n1 * h1.x + n2 * h2.x + n3 * h3.x;
        ay += n0 * h0.y + n1 * h1.y + n2 * h2.y + n3 * h3.y;
        az += n0 * h0.z + n1 * h1.z + n2 * h2.z + n3 * h3.z;
        aw += n0 * h0.w + n1 * h1.w + n2 * h2.w + n3 * h3.w;
    }
    for (; i < end; i++) {
        int2 e0 = g_csr[i];
        float4 h0 = H[e0.x * 16 + sub];
        float n0 = __int_as_float(e0.y);
        ax += n0 * h0.x; ay += n0 * h0.y; az += n0 * h0.z; aw += n0 * h0.w;
    }

    float4 bb = ((const float4*)b1)[sub];
    float4 z;
    z.x = fmaxf(ax + bb.x, 0.f);
    z.y = fmaxf(ay + bb.y, 0.f);
    z.z = fmaxf(az + bb.z, 0.f);
    z.w = fmaxf(aw + bb.w, 0.f);
    ((float4*)g_z1)[c * 16 + sub] = z;
}

// ---------------------------------------------------------------
// GEMM2: H2 = z1[NN,64] @ W2[64,32], FFMA2, vectorized X LDS.
__global__ __launch_bounds__(256) void k_gemm2(const float* __restrict__ W2) {
    __shared__ __align__(16) float Xs[128 * 68];  // 128 x (64+4)
    __shared__ __align__(16) float Ws[64 * 32];

    int nb = blockIdx.x * 128;
    int tid = threadIdx.x;

    for (int i = tid; i < 64 * 32 / 4; i += 256)
        ((float4*)Ws)[i] = ((const float4*)W2)[i];

    for (int i = tid; i < 128 * 16; i += 256) {
        int node = i >> 4, k4 = i & 15;
        int gn = nb + node;
        float4 v = make_float4(0.f, 0.f, 0.f, 0.f);
        if (gn < NN) v = ((const float4*)g_z1)[gn * 16 + k4];
        *(float4*)&Xs[node * 68 + k4 * 4] = v;
    }
    __syncthreads();

    int fg = tid & 7;   // f = fg*4 .. fg*4+3 (2 pairs)
    int ng = tid >> 3;  // node: j*32 + ng

    unsigned long long acc[4][2];
#pragma unroll
    for (int j = 0; j < 4; j++) { acc[j][0] = 0ull; acc[j][1] = 0ull; }

#pragma unroll 4
    for (int kc = 0; kc < 16; kc++) {          // 4 k per iter
        float4 xv[4];
#pragma unroll
        for (int j = 0; j < 4; j++)
            xv[j] = ((const float4*)Xs)[(j * 32 + ng) * 17 + kc];
#pragma unroll
        for (int q = 0; q < 4; q++) {
            int k = kc * 4 + q;
            ulonglong2 w = *(const ulonglong2*)&Ws[k * 32 + fg * 4];
#pragma unroll
            for (int j = 0; j < 4; j++) {
                float xs = (q == 0) ? xv[j].x : (q == 1) ? xv[j].y
                         : (q == 2) ? xv[j].z : xv[j].w;
                unsigned long long xd = pack2(xs);
                acc[j][0] = fma2(xd, w.x, acc[j][0]);
                acc[j][1] = fma2(xd, w.y, acc[j][1]);
            }
        }
    }

#pragma unroll
    for (int j = 0; j < 4; j++) {
        int gn = nb + j * 32 + ng;
        if (gn >= NN) continue;
        float2 p0 = unpack2(acc[j][0]), p1 = unpack2(acc[j][1]);
        ((float4*)g_h2)[gn * 8 + fg] = make_float4(p0.x, p0.y, p1.x, p1.y);
    }
}

// ---------------------------------------------------------------
// Gather layer 2: 8-lane group per node, float4 per lane (row = 8 x float4).
__global__ __launch_bounds__(256) void k_gather2(const float* __restrict__ b2,
                                                 float* __restrict__ out) {
    int tid = blockIdx.x * 256 + threadIdx.x;
    int c = tid >> 3;
    int sub = threadIdx.x & 7;
    if (c >= NN) return;

    const float4* H = (const float4*)g_h2;     // row stride 8
    float di = g_dinv[c];
    float d2 = di * di;
    float4 hc = H[c * 8 + sub];
    float ax = d2 * hc.x, ay = d2 * hc.y, az = d2 * hc.z, aw = d2 * hc.w;

    int i = g_off[c], end = g_off[c + 1];
    for (; i + 3 < end; i += 4) {
        int2 e0 = g_csr[i],     e1 = g_csr[i + 1];
        int2 e2 = g_csr[i + 2], e3 = g_csr[i + 3];
        float4 h0 = H[e0.x * 8 + sub];
        float4 h1 = H[e1.x * 8 + sub];
        float4 h2 = H[e2.x * 8 + sub];
        float4 h3 = H[e3.x * 8 + sub];
        float n0 = __int_as_float(e0.y), n1 = __int_as_float(e1.y);
        float n2 = __int_as_float(e2.y), n3 = __int_as_float(e3.y);
        ax += n0 * h0.x + n1 * h1.x + n2 * h2.x + n3 * h3.x;
        ay += n0 * h0.y + n1 * h1.y + n2 * h2.y + n3 * h3.y;
        az += n0 * h0.z + n1 * h1.z + n2 * h2.z + n3 * h3.z;
        aw += n0 * h0.w + n1 * h1.w + n2 * h2.w + n3 * h3.w;
    }
    for (; i < end; i++) {
        int2 e0 = g_csr[i];
        float4 h0 = H[e0.x * 8 + sub];
        float n0 = __int_as_float(e0.y);
        ax += n0 * h0.x; ay += n0 * h0.y; az += n0 * h0.z; aw += n0 * h0.w;
    }

    float4 bb = ((const float4*)b2)[sub];
    ((float4*)out)[c * 8 + sub] =
        make_float4(ax + bb.x, ay + bb.y, az + bb.z, aw + bb.w);
}

// ---------------------------------------------------------------
static const void* by_size(void* const* d_in, const int* in_sizes, int n_in,
                           long long want) {
    for (int i = 0; i < n_in; i++)
        if ((long long)in_sizes[i] == want) return d_in[i];
    return 0;
}

extern "C" void kernel_launch(void* const* d_in, const int* in_sizes, int n_in,
                              void* d_out, int out_size) {
    const float* x  = (const float*)by_size(d_in, in_sizes, n_in, (long long)NN * INF);   // 12.8M
    const void*  ei =               by_size(d_in, in_sizes, n_in, 2LL * NE);              // 3.2M
    const float* ew = (const float*)by_size(d_in, in_sizes, n_in, (long long)NE);         // 1.6M
    const float* W1 = (const float*)by_size(d_in, in_sizes, n_in, (long long)INF * HF);   // 8192
    const float* b1 = (const float*)by_size(d_in, in_sizes, n_in, (long long)HF);         // 64
    const float* W2 = (const float*)by_size(d_in, in_sizes, n_in, (long long)HF * OUTF);  // 2048
    const float* b2 = (const float*)by_size(d_in, in_sizes, n_in, (long long)OUTF);       // 32
    float* out = (float*)d_out;

    cudaFuncSetAttribute(k_gemm1, cudaFuncAttributeMaxDynamicSharedMemorySize, G1_SMEM);

    // Profiled launch is the 4th of this sequence -> k_prep.
    k_initA  <<<(NN + 255) / 256, 256>>>();                         // 1
    k_initB  <<<1, 256>>>((const unsigned int*)ei);                 // 2
    k_gemm1  <<<(NN + 127) / 128, 256, G1_SMEM>>>(x, W1);           // 3
    k_prep   <<<PREP_G, PREP_B>>>((const int*)ei, ew);              // 4 <- profiled
    k_gather1<<<(NN * 16 + 255) / 256, 256>>>(b1);                  // 5
    k_gemm2  <<<(NN + 127) / 128, 256>>>(W2);                       // 6
    k_gather2<<<(NN * 8 + 255) / 256, 256>>>(b2, out);              // 7
}

// round 10
// speedup vs baseline: 1.0124x; 1.0124x over previous
#include <cuda_runtime.h>

#define NN   100000
#define NE   1600000
#define INF  128
#define HF   64
#define OUTF 32

#define PREP_B   256
#define PREP_G   592                      // 4 per SM on 148 SMs: all co-resident
#define NPB      ((NN + PREP_G - 1) / PREP_G)   // 169 nodes per block

// ---- scratch (static device globals; no allocation anywhere) ----
__device__ __align__(16) float g_deg   [NN];
__device__ __align__(16) float g_dinv  [NN];
__device__ __align__(16) int   g_cnt   [NN];      // in-degree histogram (by col)
__device__ __align__(16) int   g_off   [NN + 1];  // CSR offsets (exclusive)
__device__ __align__(16) int   g_bsum  [PREP_G];  // per-block count totals
__device__ __align__(16) int4  g_rco   [NE];      // (row, col, ordinal, ew-bits)
__device__ __align__(16) int2  g_csr   [NE];      // packed (src_row, norm-bits)
__device__ __align__(16) float g_h1 [NN * HF];    // X @ W1
__device__ __align__(16) float g_z1 [NN * HF];    // relu(agg1 + b1)
__device__ __align__(16) float g_h2 [NN * OUTF];  // z1 @ W2
__device__ unsigned int g_flag;                   // 0 = int64 edge_index, 1 = int32

// ---- packed f32x2 helpers (Blackwell FFMA2) ----
__device__ __forceinline__ unsigned long long pack2(float x) {
    unsigned long long r;
    asm("mov.b64 %0, {%1, %2};" : "=l"(r) : "f"(x), "f"(x));
    return r;
}
__device__ __forceinline__ unsigned long long fma2(unsigned long long a,
                                                   unsigned long long b,
                                                   unsigned long long c) {
    unsigned long long d;
    asm("fma.rn.f32x2 %0, %1, %2, %3;" : "=l"(d) : "l"(a), "l"(b), "l"(c));
    return d;
}
__device__ __forceinline__ float2 unpack2(unsigned long long v) {
    float lo, hi;
    asm("mov.b64 {%0, %1}, %2;" : "=f"(lo), "=f"(hi) : "l"(v));
    return make_float2(lo, hi);
}

// ---- software grid barrier (all PREP_G blocks resident by construction) ----
__device__ unsigned g_bar_count = 0;
__device__ volatile unsigned g_bar_gen = 0;

__device__ __forceinline__ void grid_barrier() {
    __syncthreads();
    if (threadIdx.x == 0) {
        unsigned gen = g_bar_gen;
        __threadfence();
        if (atomicAdd(&g_bar_count, 1u) == PREP_G - 1) {
            g_bar_count = 0;
            __threadfence();
            g_bar_gen = gen + 1;
        } else {
            while (g_bar_gen == gen) { }
            __threadfence();
        }
    }
    __syncthreads();
}

// ---------------------------------------------------------------
// initA: per-call scratch init.
__global__ void k_initA() {
    int i = blockIdx.x * 256 + threadIdx.x;
    if (i < NN) {
        g_deg[i] = 1.0f;    // self-loop weight
        g_cnt[i] = 0;
    }
    if (i == 0) g_flag = 0u;
}

// initB: sampled dtype detect. int64 (values in [0,2^31)): odd u32 words all 0.
__global__ void k_initB(const unsigned int* __restrict__ ei32) {
    int s = (int)threadIdx.x * (NE / 256) + 1;   // 256 spread samples
    if (ei32[2 * s + 1] != 0u) atomicOr(&g_flag, 1u);
}

// ---------------------------------------------------------------
// k_prep: histogram+ordinal -> bar -> dinv+scan -> bar -> prefix -> bar ->
//         atomic-free CSR fill.
__global__ __launch_bounds__(PREP_B) void k_prep(const int* __restrict__ ei32,
                                                 const float* __restrict__ ew) {
    int t = threadIdx.x, b = blockIdx.x;
    int lane = t & 31, wid = t >> 5;
    const int S = PREP_G * PREP_B;
    int flag = g_flag;

    // --- phase 1: decode, histogram, ordinal capture (batched x4 for MLP) ---
    {
        int e = b * PREP_B + t;
        for (; e + 3 * S < NE; e += 4 * S) {
            int e1 = e + S, e2 = e + 2 * S, e3 = e + 3 * S;
            int r0, c0, r1, c1, r2, c2, r3, c3;
            if (flag) {
                r0 = ei32[e];  c0 = ei32[NE + e];
                r1 = ei32[e1]; c1 = ei32[NE + e1];
                r2 = ei32[e2]; c2 = ei32[NE + e2];
                r3 = ei32[e3]; c3 = ei32[NE + e3];
            } else {
                r0 = ei32[2 * e];  c0 = ei32[2 * (NE + e)];
                r1 = ei32[2 * e1]; c1 = ei32[2 * (NE + e1)];
                r2 = ei32[2 * e2]; c2 = ei32[2 * (NE + e2)];
                r3 = ei32[2 * e3]; c3 = ei32[2 * (NE + e3)];
            }
            float w0 = ew[e], w1 = ew[e1], w2 = ew[e2], w3 = ew[e3];
            int o0 = atomicAdd(&g_cnt[c0], 1);
            int o1 = atomicAdd(&g_cnt[c1], 1);
            int o2 = atomicAdd(&g_cnt[c2], 1);
            int o3 = atomicAdd(&g_cnt[c3], 1);
            atomicAdd(&g_deg[c0], w0);
            atomicAdd(&g_deg[c1], w1);
            atomicAdd(&g_deg[c2], w2);
            atomicAdd(&g_deg[c3], w3);
            g_rco[e]  = make_int4(r0, c0, o0, __float_as_int(w0));
            g_rco[e1] = make_int4(r1, c1, o1, __float_as_int(w1));
            g_rco[e2] = make_int4(r2, c2, o2, __float_as_int(w2));
            g_rco[e3] = make_int4(r3, c3, o3, __float_as_int(w3));
        }
        for (; e < NE; e += S) {
            int r, c;
            if (flag) { r = ei32[e];     c = ei32[NE + e]; }
            else      { r = ei32[2 * e]; c = ei32[2 * (NE + e)]; }
            float w = ew[e];
            int o = atomicAdd(&g_cnt[c], 1);
            atomicAdd(&g_deg[c], w);
            g_rco[e] = make_int4(r, c, o, __float_as_int(w));
        }
    }

    grid_barrier();

    // --- phase 2: dinv + per-block scan ---
    int i = b * NPB + t;                       // NPB=169 < 256
    bool valid = (t < NPB) && (i < NN);

    if (valid) g_dinv[i] = rsqrtf(g_deg[i]);   // deg >= 1 always

    int v = valid ? g_cnt[i] : 0;

    int val = v;
#pragma unroll
    for (int s = 1; s < 32; s <<= 1) {
        int u = __shfl_up_sync(0xffffffffu, val, s);
        if (lane >= s) val += u;
    }
    __shared__ int wsum[8];
    if (lane == 31) wsum[wid] = val;
    __syncthreads();
    __shared__ int wexc[8];
    if (t == 0) {
        int s = 0;
#pragma unroll
        for (int w = 0; w < 8; w++) { wexc[w] = s; s += wsum[w]; }
        g_bsum[b] = s;                          // block total
    }
    __syncthreads();
    int excl = wexc[wid] + val - v;
    if (valid) g_off[i] = excl;                 // local exclusive (prefix later)

    grid_barrier();

    // --- phase 3: cross-block prefix (each block redundantly) ---
    __shared__ int red[PREP_B];
    int p = 0;
    for (int j = t; j < b; j += PREP_B) p += g_bsum[j];
    red[t] = p;
    __syncthreads();
#pragma unroll
    for (int s = 128; s > 0; s >>= 1) {
        if (t < s) red[t] += red[t + s];
        __syncthreads();
    }
    int prefix = red[0];
    if (valid) g_off[i] += prefix;
    if (b == 0 && t == 0) g_off[NN] = NE;

    grid_barrier();

    // --- phase 4: atomic-free CSR fill (batched x4 for MLP) ---
    {
        int e = b * PREP_B + t;
        for (; e + 3 * S < NE; e += 4 * S) {
            int4 a0 = g_rco[e];
            int4 a1 = g_rco[e + S];
            int4 a2 = g_rco[e + 2 * S];
            int4 a3 = g_rco[e + 3 * S];
            float dr0 = g_dinv[a0.x], dc0 = g_dinv[a0.y];
            float dr1 = g_dinv[a1.x], dc1 = g_dinv[a1.y];
            float dr2 = g_dinv[a2.x], dc2 = g_dinv[a2.y];
            float dr3 = g_dinv[a3.x], dc3 = g_dinv[a3.y];
            int p0 = g_off[a0.y] + a0.z;
            int p1 = g_off[a1.y] + a1.z;
            int p2 = g_off[a2.y] + a2.z;
            int p3 = g_off[a3.y] + a3.z;
            g_csr[p0] = make_int2(a0.x, __float_as_int(dr0 * __int_as_float(a0.w) * dc0));
            g_csr[p1] = make_int2(a1.x, __float_as_int(dr1 * __int_as_float(a1.w) * dc1));
            g_csr[p2] = make_int2(a2.x, __float_as_int(dr2 * __int_as_float(a2.w) * dc2));
            g_csr[p3] = make_int2(a3.x, __float_as_int(dr3 * __int_as_float(a3.w) * dc3));
        }
        for (; e < NE; e += S) {
            int4 a = g_rco[e];
            float nm = g_dinv[a.x] * __int_as_float(a.w) * g_dinv[a.y];
            g_csr[g_off[a.y] + a.z] = make_int2(a.x, __float_as_int(nm));
        }
    }
}

// ---------------------------------------------------------------
// GEMM1: H1 = X[NN,128] @ W1[128,64], FFMA2, occupancy-tuned (3 blocks/SM).
#define G1_XS    (128 * 68)
#define G1_WS    (8 * 1028)
#define G1_SMEM  ((G1_XS + G1_WS) * 4)         // 67712 B

__global__ __launch_bounds__(256, 3) void k_gemm1(const float* __restrict__ x,
                                                  const float* __restrict__ W1) {
    extern __shared__ float sh[];
    float* Xs  = sh;           // [128][68]
    float* Wsh = sh + G1_XS;   // [8][1028]  (fg-major, 8 floats per k, pad 4)

    int nb = blockIdx.x * 128;
    int tid = threadIdx.x;
    int fg = tid & 7;          // output pairs: f = fg*8 .. fg*8+7
    int ng = tid >> 3;         // 0..31; nodes: j*32 + ng

    for (int i = tid; i < 128 * 16; i += 256) {
        int k = i >> 4, c = i & 15;
        int fgw = c >> 1, half = (c & 1) * 4;
        float4 v = ((const float4*)W1)[i];
        *(float4*)&Wsh[fgw * 1028 + k * 8 + half] = v;
    }

    unsigned long long acc[4][4];
#pragma unroll
    for (int j = 0; j < 4; j++)
#pragma unroll
        for (int p = 0; p < 4; p++) acc[j][p] = 0ull;

#pragma unroll
    for (int stage = 0; stage < 2; stage++) {
        for (int i = tid; i < 128 * 16; i += 256) {
            int node = i >> 4, kc = i & 15;
            int gn = nb + node;
            float4 v = make_float4(0.f, 0.f, 0.f, 0.f);
            if (gn < NN) v = ((const float4*)x)[gn * 32 + stage * 16 + kc];
            *(float4*)&Xs[node * 68 + kc * 4] = v;
        }
        __syncthreads();

#pragma unroll 2
        for (int kc = 0; kc < 16; kc++) {
            float4 xv[4];
#pragma unroll
            for (int j = 0; j < 4; j++)
                xv[j] = ((const float4*)Xs)[(j * 32 + ng) * 17 + kc];
#pragma unroll
            for (int q = 0; q < 4; q++) {
                int kf = stage * 64 + kc * 4 + q;
                const float* wp = &Wsh[fg * 1028 + kf * 8];
                ulonglong2 wa = *(const ulonglong2*)wp;
                ulonglong2 wb = *(const ulonglong2*)(wp + 4);
#pragma unroll
                for (int j = 0; j < 4; j++) {
                    float xs = (q == 0) ? xv[j].x : (q == 1) ? xv[j].y
                             : (q == 2) ? xv[j].z : xv[j].w;
                    unsigned long long xd = pack2(xs);
                    acc[j][0] = fma2(xd, wa.x, acc[j][0]);
                    acc[j][1] = fma2(xd, wa.y, acc[j][1]);
                    acc[j][2] = fma2(xd, wb.x, acc[j][2]);
                    acc[j][3] = fma2(xd, wb.y, acc[j][3]);
                }
            }
        }
        __syncthreads();
    }

#pragma unroll
    for (int j = 0; j < 4; j++) {
        int gn = nb + j * 32 + ng;
        if (gn >= NN) continue;
        float2 p0 = unpack2(acc[j][0]), p1 = unpack2(acc[j][1]);
        float2 p2 = unpack2(acc[j][2]), p3 = unpack2(acc[j][3]);
        ((float4*)g_h1)[gn * 16 + fg * 2]     = make_float4(p0.x, p0.y, p1.x, p1.y);
        ((float4*)g_h1)[gn * 16 + fg * 2 + 1] = make_float4(p2.x, p2.y, p3.x, p3.y);
    }
}

// ---------------------------------------------------------------
// Gather layer 1: 16-lane group per node, float4 per lane (row = 16 x float4).
__global__ __launch_bounds__(256) void k_gather1(const float* __restrict__ b1) {
    int tid = blockIdx.x * 256 + threadIdx.x;
    int c = tid >> 4;
    int sub = threadIdx.x & 15;
    if (c >= NN) return;

    const float4* H = (const float4*)g_h1;     // row stride 16
    float di = g_dinv[c];
    float d2 = di * di;
    float4 hc = H[c * 16 + sub];
    float ax = d2 * hc.x, ay = d2 * hc.y, az = d2 * hc.z, aw = d2 * hc.w;

    int i = g_off[c], end = g_off[c + 1];
    for (; i + 3 < end; i += 4) {
        int2 e0 = g_csr[i],     e1 = g_csr[i + 1];
        int2 e2 = g_csr[i + 2], e3 = g_csr[i + 3];
        float4 h0 = H[e0.x * 16 + sub];
        float4 h1 = H[e1.x * 16 + sub];
        float4 h2 = H[e2.x * 16 + sub];
        float4 h3 = H[e3.x * 16 + sub];
        float n0 = __int_as_float(e0.y), n1 = __int_as_float(e1.y);
        float n2 = __int_as_float(e2.y), n3 = __int_as_float(e3.y);
        ax += n0 * h0.x + n1 * h1.x + n2 * h2.x + n3 * h3.x;
        ay += n0 * h0.y + n1 * h1.y + n2 * h2.y + n3 * h3.y;
        az += n0 * h0.z + n1 * h1.z + n2 * h2.z + n3 * h3.z;
        aw += n0 * h0.w + n1 * h1.w + n2 * h2.w + n3 * h3.w;
    }
    for (; i < end; i++) {
        int2 e0 = g_csr[i];
        float4 h0 = H[e0.x * 16 + sub];
        float n0 = __int_as_float(e0.y);
        ax += n0 * h0.x; ay += n0 * h0.y; az += n0 * h0.z; aw += n0 * h0.w;
    }

    float4 bb = ((const float4*)b1)[sub];
    float4 z;
    z.x = fmaxf(ax + bb.x, 0.f);
    z.y = fmaxf(ay + bb.y, 0.f);
    z.z = fmaxf(az + bb.z, 0.f);
    z.w = fmaxf(aw + bb.w, 0.f);
    ((float4*)g_z1)[c * 16 + sub] = z;
}

// ---------------------------------------------------------------
// GEMM2: H2 = z1[NN,64] @ W2[64,32], FFMA2, vectorized X LDS.
__global__ __launch_bounds__(256) void k_gemm2(const float* __restrict__ W2) {
    __shared__ __align__(16) float Xs[128 * 68];  // 128 x (64+4)
    __shared__ __align__(16) float Ws[64 * 32];

    int nb = blockIdx.x * 128;
    int tid = threadIdx.x;

    for (int i = tid; i < 64 * 32 / 4; i += 256)
        ((float4*)Ws)[i] = ((const float4*)W2)[i];

    for (int i = tid; i < 128 * 16; i += 256) {
        int node = i >> 4, k4 = i & 15;
        int gn = nb + node;
        float4 v = make_float4(0.f, 0.f, 0.f, 0.f);
        if (gn < NN) v = ((const float4*)g_z1)[gn * 16 + k4];
        *(float4*)&Xs[node * 68 + k4 * 4] = v;
    }
    __syncthreads();

    int fg = tid & 7;   // f = fg*4 .. fg*4+3 (2 pairs)
    int ng = tid >> 3;  // node: j*32 + ng

    unsigned long long acc[4][2];
#pragma unroll
    for (int j = 0; j < 4; j++) { acc[j][0] = 0ull; acc[j][1] = 0ull; }

#pragma unroll 4
    for (int kc = 0; kc < 16; kc++) {
        float4 xv[4];
#pragma unroll
        for (int j = 0; j < 4; j++)
            xv[j] = ((const float4*)Xs)[(j * 32 + ng) * 17 + kc];
#pragma unroll
        for (int q = 0; q < 4; q++) {
            int k = kc * 4 + q;
            ulonglong2 w = *(const ulonglong2*)&Ws[k * 32 + fg * 4];
#pragma unroll
            for (int j = 0; j < 4; j++) {
                float xs = (q == 0) ? xv[j].x : (q == 1) ? xv[j].y
                         : (q == 2) ? xv[j].z : xv[j].w;
                unsigned long long xd = pack2(xs);
                acc[j][0] = fma2(xd, w.x, acc[j][0]);
                acc[j][1] = fma2(xd, w.y, acc[j][1]);
            }
        }
    }

#pragma unroll
    for (int j = 0; j < 4; j++) {
        int gn = nb + j * 32 + ng;
        if (gn >= NN) continue;
        float2 p0 = unpack2(acc[j][0]), p1 = unpack2(acc[j][1]);
        ((float4*)g_h2)[gn * 8 + fg] = make_float4(p0.x, p0.y, p1.x, p1.y);
    }
}

// ---------------------------------------------------------------
// Gather layer 2: 8-lane group per node, float4 per lane (row = 8 x float4).
__global__ __launch_bounds__(256) void k_gather2(const float* __restrict__ b2,
                                                 float* __restrict__ out) {
    int tid = blockIdx.x * 256 + threadIdx.x;
    int c = tid >> 3;
    int sub = threadIdx.x & 7;
    if (c >= NN) return;

    const float4* H = (const float4*)g_h2;     // row stride 8
    float di = g_dinv[c];
    float d2 = di * di;
    float4 hc = H[c * 8 + sub];
    float ax = d2 * hc.x, ay = d2 * hc.y, az = d2 * hc.z, aw = d2 * hc.w;

    int i = g_off[c], end = g_off[c + 1];
    for (; i + 3 < end; i += 4) {
        int2 e0 = g_csr[i],     e1 = g_csr[i + 1];
        int2 e2 = g_csr[i + 2], e3 = g_csr[i + 3];
        float4 h0 = H[e0.x * 8 + sub];
        float4 h1 = H[e1.x * 8 + sub];
        float4 h2 = H[e2.x * 8 + sub];
        float4 h3 = H[e3.x * 8 + sub];
        float n0 = __int_as_float(e0.y), n1 = __int_as_float(e1.y);
        float n2 = __int_as_float(e2.y), n3 = __int_as_float(e3.y);
        ax += n0 * h0.x + n1 * h1.x + n2 * h2.x + n3 * h3.x;
        ay += n0 * h0.y + n1 * h1.y + n2 * h2.y + n3 * h3.y;
        az += n0 * h0.z + n1 * h1.z + n2 * h2.z + n3 * h3.z;
        aw += n0 * h0.w + n1 * h1.w + n2 * h2.w + n3 * h3.w;
    }
    for (; i < end; i++) {
        int2 e0 = g_csr[i];
        float4 h0 = H[e0.x * 8 + sub];
        float n0 = __int_as_float(e0.y);
        ax += n0 * h0.x; ay += n0 * h0.y; az += n0 * h0.z; aw += n0 * h0.w;
    }

    float4 bb = ((const float4*)b2)[sub];
    ((float4*)out)[c * 8 + sub] =
        make_float4(ax + bb.x, ay + bb.y, az + bb.z, aw + bb.w);
}

// ---------------------------------------------------------------
static const void* by_size(void* const* d_in, const int* in_sizes, int n_in,
                           long long want) {
    for (int i = 0; i < n_in; i++)
        if ((long long)in_sizes[i] == want) return d_in[i];
    return 0;
}

extern "C" void kernel_launch(void* const* d_in, const int* in_sizes, int n_in,
                              void* d_out, int out_size) {
    const float* x  = (const float*)by_size(d_in, in_sizes, n_in, (long long)NN * INF);   // 12.8M
    const void*  ei =               by_size(d_in, in_sizes, n_in, 2LL * NE);              // 3.2M
    const float* ew = (const float*)by_size(d_in, in_sizes, n_in, (long long)NE);         // 1.6M
    const float* W1 = (const float*)by_size(d_in, in_sizes, n_in, (long long)INF * HF);   // 8192
    const float* b1 = (const float*)by_size(d_in, in_sizes, n_in, (long long)HF);         // 64
    const float* W2 = (const float*)by_size(d_in, in_sizes, n_in, (long long)HF * OUTF);  // 2048
    const float* b2 = (const float*)by_size(d_in, in_sizes, n_in, (long long)OUTF);       // 32
    float* out = (float*)d_out;

    cudaFuncSetAttribute(k_gemm1, cudaFuncAttributeMaxDynamicSharedMemorySize, G1_SMEM);

    // Profiled launch is the 4th of this sequence -> k_prep.
    k_initA  <<<(NN + 255) / 256, 256>>>();                         // 1
    k_initB  <<<1, 256>>>((const unsigned int*)ei);                 // 2
    k_gemm1  <<<(NN + 127) / 128, 256, G1_SMEM>>>(x, W1);           // 3
    k_prep   <<<PREP_G, PREP_B>>>((const int*)ei, ew);              // 4 <- profiled
    k_gather1<<<(NN * 16 + 255) / 256, 256>>>(b1);                  // 5
    k_gemm2  <<<(NN + 127) / 128, 256>>>(W2);                       // 6
    k_gather2<<<(NN * 8 + 255) / 256, 256>>>(b2, out);              // 7
}